// round 1
// baseline (speedup 1.0000x reference)
#include <cuda_runtime.h>
#include <cuda_bf16.h>
#include <cstdint>

#define N_NODES 100000
#define NE      1600000
#define ETOT    (NE + N_NODES)
#define NG      256
#define IN_DIM  480
#define HID     128
#define HEADS   4
#define HEAD_DIM 32
#define NEG_SLOPE 0.2f
#define LN_EPS 1e-5f
#define FULLMASK 0xffffffffu

// ---------------- scratch (static device globals; no allocation) ----------------
__device__ __align__(16) float g_h [N_NODES * HID];
__device__ __align__(16) float g_hp[N_NODES * HID];
__device__ __align__(16) float g_asrc[N_NODES * HEADS];
__device__ __align__(16) float g_adst[N_NODES * HEADS];
__device__ int g_deg[N_NODES];
__device__ int g_rowptr[N_NODES + 1];
__device__ int g_cursor[N_NODES];
__device__ int g_csr_src[ETOT];
__device__ int g_bsums[256];
__device__ int g_gcnt[NG];
__device__ int g_gstart[NG + 1];

// ---------------- small utility kernels ----------------
__global__ void k_zero() {
    int i = blockIdx.x * blockDim.x + threadIdx.x;
    if (i < N_NODES) g_deg[i] = 0;
    if (i < NG) g_gcnt[i] = 0;
}

__global__ void k_ehist(const int* __restrict__ ei) {
    int i = blockIdx.x * blockDim.x + threadIdx.x;
    if (i >= ETOT) return;
    int d = (i < NE) ? ei[NE + i] : (i - NE);
    atomicAdd(&g_deg[d], 1);
}

__global__ void k_ghist(const int* __restrict__ batch) {
    int i = blockIdx.x * blockDim.x + threadIdx.x;
    if (i < N_NODES) atomicAdd(&g_gcnt[batch[i]], 1);
}

#define SCAN_B 512
__global__ void k_scan1() {
    __shared__ int sm[SCAN_B];
    int t = threadIdx.x;
    int i = blockIdx.x * SCAN_B + t;
    int v = (i < N_NODES) ? g_deg[i] : 0;
    sm[t] = v; __syncthreads();
    for (int o = 1; o < SCAN_B; o <<= 1) {
        int u = (t >= o) ? sm[t - o] : 0;
        __syncthreads();
        sm[t] += u;
        __syncthreads();
    }
    if (i < N_NODES) g_rowptr[i + 1] = sm[t];
    if (t == SCAN_B - 1) g_bsums[blockIdx.x] = sm[t];
}

__global__ void k_scan2(int nb) {
    __shared__ int sm[256];
    int t = threadIdx.x;
    int v = (t < nb) ? g_bsums[t] : 0;
    sm[t] = v; __syncthreads();
    for (int o = 1; o < 256; o <<= 1) {
        int u = (t >= o) ? sm[t - o] : 0;
        __syncthreads();
        sm[t] += u;
        __syncthreads();
    }
    if (t < nb) g_bsums[t] = sm[t] - v;  // exclusive
}

__global__ void k_scan3() {
    int i = blockIdx.x * SCAN_B + threadIdx.x;
    if (i < N_NODES) g_rowptr[i + 1] += g_bsums[blockIdx.x];
    if (i == 0) g_rowptr[0] = 0;
}

__global__ void k_copy_cursor() {
    int i = blockIdx.x * blockDim.x + threadIdx.x;
    if (i < N_NODES) g_cursor[i] = g_rowptr[i];
}

__global__ void k_fill(const int* __restrict__ ei) {
    int i = blockIdx.x * blockDim.x + threadIdx.x;
    if (i >= ETOT) return;
    int s, d;
    if (i < NE) { s = ei[i]; d = ei[NE + i]; }
    else        { s = d = i - NE; }
    int pos = atomicAdd(&g_cursor[d], 1);
    g_csr_src[pos] = s;
}

__global__ void k_gscan() {
    __shared__ int sm[NG];
    int t = threadIdx.x;
    int v = g_gcnt[t];
    sm[t] = v; __syncthreads();
    for (int o = 1; o < NG; o <<= 1) {
        int u = (t >= o) ? sm[t - o] : 0;
        __syncthreads();
        sm[t] += u;
        __syncthreads();
    }
    g_gstart[t] = sm[t] - v;
    if (t == NG - 1) g_gstart[NG] = sm[t];
}

// ---------------- tf32 tensor-core GEMM: C[M,128] = A[M,K] @ B[K,128] ----------------
__device__ __forceinline__ float f2tf32(float x) {
    asm("cvt.rna.tf32.f32 %0, %1;" : "=f"(x) : "f"(x));
    return x;
}

__device__ __forceinline__ void mma_tf32(float* c, const unsigned* a, const unsigned* b) {
    asm volatile(
        "mma.sync.aligned.m16n8k8.row.col.f32.tf32.tf32.f32 "
        "{%0,%1,%2,%3},{%4,%5,%6,%7},{%8,%9},{%0,%1,%2,%3};\n"
        : "+f"(c[0]), "+f"(c[1]), "+f"(c[2]), "+f"(c[3])
        : "r"(a[0]), "r"(a[1]), "r"(a[2]), "r"(a[3]), "r"(b[0]), "r"(b[1]));
}

template <int KD, bool RELU_BIAS>
__global__ __launch_bounds__(256) void gemm_tf32(
    const float* __restrict__ A, const float* __restrict__ B,
    const float* __restrict__ bias, float* __restrict__ C)
{
    constexpr int BM = 128, BN = 128, BK = 16;
    __shared__ float As[BK][BM + 4];
    __shared__ float Bs[BK][BN + 4];
    int tid = threadIdx.x;
    int warp = tid >> 5, lane = tid & 31;
    int wm = warp >> 1, wn = warp & 1;
    int gid = lane >> 2, tg = lane & 3;
    int rowBase = blockIdx.x * BM;

    float acc[2][8][4];
#pragma unroll
    for (int mf = 0; mf < 2; mf++)
#pragma unroll
        for (int nf = 0; nf < 8; nf++)
#pragma unroll
            for (int q = 0; q < 4; q++) acc[mf][nf][q] = 0.f;

    for (int k0 = 0; k0 < KD; k0 += BK) {
        __syncthreads();
        // A tile 128x16 -> As[k][m]
#pragma unroll
        for (int it = 0; it < 2; it++) {
            int idx = tid + it * 256;
            int r = idx >> 2, c4 = (idx & 3) * 4;
            int grow = rowBase + r;
            float4 v = make_float4(0.f, 0.f, 0.f, 0.f);
            if (grow < N_NODES) v = *(const float4*)(A + grow * KD + k0 + c4);
            As[c4 + 0][r] = f2tf32(v.x);
            As[c4 + 1][r] = f2tf32(v.y);
            As[c4 + 2][r] = f2tf32(v.z);
            As[c4 + 3][r] = f2tf32(v.w);
        }
        // B tile 16x128 -> Bs[k][n]
#pragma unroll
        for (int it = 0; it < 2; it++) {
            int idx = tid + it * 256;
            int r = idx >> 5, c4 = (idx & 31) * 4;
            float4 v = *(const float4*)(B + (k0 + r) * BN + c4);
            Bs[r][c4 + 0] = f2tf32(v.x);
            Bs[r][c4 + 1] = f2tf32(v.y);
            Bs[r][c4 + 2] = f2tf32(v.z);
            Bs[r][c4 + 3] = f2tf32(v.w);
        }
        __syncthreads();
#pragma unroll
        for (int ks = 0; ks < 2; ks++) {
            int kb = ks * 8;
            unsigned afr[2][4];
            unsigned bfr[8][2];
#pragma unroll
            for (int mf = 0; mf < 2; mf++) {
                int m = wm * 32 + mf * 16;
                afr[mf][0] = __float_as_uint(As[kb + tg][m + gid]);
                afr[mf][1] = __float_as_uint(As[kb + tg][m + gid + 8]);
                afr[mf][2] = __float_as_uint(As[kb + tg + 4][m + gid]);
                afr[mf][3] = __float_as_uint(As[kb + tg + 4][m + gid + 8]);
            }
#pragma unroll
            for (int nf = 0; nf < 8; nf++) {
                int n = wn * 64 + nf * 8;
                bfr[nf][0] = __float_as_uint(Bs[kb + tg][n + gid]);
                bfr[nf][1] = __float_as_uint(Bs[kb + tg + 4][n + gid]);
            }
#pragma unroll
            for (int mf = 0; mf < 2; mf++)
#pragma unroll
                for (int nf = 0; nf < 8; nf++)
                    mma_tf32(acc[mf][nf], afr[mf], bfr[nf]);
        }
    }
    // epilogue
#pragma unroll
    for (int mf = 0; mf < 2; mf++) {
        int r0 = rowBase + wm * 32 + mf * 16 + gid;
#pragma unroll
        for (int nf = 0; nf < 8; nf++) {
            int c = wn * 64 + nf * 8 + tg * 2;
            float2 v0 = make_float2(acc[mf][nf][0], acc[mf][nf][1]);
            float2 v1 = make_float2(acc[mf][nf][2], acc[mf][nf][3]);
            if (RELU_BIAS) {
                float b0 = __ldg(bias + c), b1 = __ldg(bias + c + 1);
                v0.x = fmaxf(v0.x + b0, 0.f); v0.y = fmaxf(v0.y + b1, 0.f);
                v1.x = fmaxf(v1.x + b0, 0.f); v1.y = fmaxf(v1.y + b1, 0.f);
            }
            if (r0 < N_NODES)     *(float2*)(C + r0 * 128 + c) = v0;
            if (r0 + 8 < N_NODES) *(float2*)(C + (r0 + 8) * 128 + c) = v1;
        }
    }
}

// ---------------- attention scores: asrc/adst [N,4] from hp ----------------
__global__ void k_scores(const float* __restrict__ att_s, const float* __restrict__ att_d) {
    int gi = blockIdx.x * blockDim.x + threadIdx.x;
    int n = gi >> 5;
    if (n >= N_NODES) return;
    int lane = threadIdx.x & 31;
    float4 v  = *(const float4*)(g_hp + n * 128 + lane * 4);
    float4 as = *(const float4*)(att_s + lane * 4);
    float4 ad = *(const float4*)(att_d + lane * 4);
    float ss = v.x * as.x + v.y * as.y + v.z * as.z + v.w * as.w;
    float sd = v.x * ad.x + v.y * ad.y + v.z * ad.z + v.w * ad.w;
#pragma unroll
    for (int o = 4; o > 0; o >>= 1) {
        ss += __shfl_down_sync(FULLMASK, ss, o);
        sd += __shfl_down_sync(FULLMASK, sd, o);
    }
    if ((lane & 7) == 0) {
        g_asrc[n * 4 + (lane >> 3)] = ss;
        g_adst[n * 4 + (lane >> 3)] = sd;
    }
}

// ---------------- fused GAT aggregation + bias + LN + relu + residual ----------------
__device__ __forceinline__ float lrelu(float x) { return x > 0.f ? x : NEG_SLOPE * x; }

__global__ __launch_bounds__(256) void k_agg(
    const float* __restrict__ bgat, const float* __restrict__ lng, const float* __restrict__ lnb)
{
    int n = (blockIdx.x * blockDim.x + threadIdx.x) >> 5;
    if (n >= N_NODES) return;
    int lane = threadIdx.x & 31;
    int beg = g_rowptr[n], end = g_rowptr[n + 1];
    float4 adst4 = *(const float4*)(g_adst + n * 4);

    // pass 1: per-head max over incoming edges (lane-parallel)
    float m0 = -1e30f, m1 = -1e30f, m2 = -1e30f, m3 = -1e30f;
    for (int j = beg + lane; j < end; j += 32) {
        int s = g_csr_src[j];
        float4 a4 = *(const float4*)(g_asrc + s * 4);
        m0 = fmaxf(m0, lrelu(a4.x + adst4.x));
        m1 = fmaxf(m1, lrelu(a4.y + adst4.y));
        m2 = fmaxf(m2, lrelu(a4.z + adst4.z));
        m3 = fmaxf(m3, lrelu(a4.w + adst4.w));
    }
#pragma unroll
    for (int o = 16; o > 0; o >>= 1) {
        m0 = fmaxf(m0, __shfl_xor_sync(FULLMASK, m0, o));
        m1 = fmaxf(m1, __shfl_xor_sync(FULLMASK, m1, o));
        m2 = fmaxf(m2, __shfl_xor_sync(FULLMASK, m2, o));
        m3 = fmaxf(m3, __shfl_xor_sync(FULLMASK, m3, o));
    }
    int myh = lane >> 3;

    // pass 2: accumulate exp-weighted features + denominator
    float a0 = 0.f, a1 = 0.f, a2 = 0.f, a3 = 0.f, den = 0.f;
    for (int jb = beg; jb < end; jb += 32) {
        int j = jb + lane;
        int s_l = 0;
        float x0 = 0.f, x1 = 0.f, x2 = 0.f, x3 = 0.f;
        if (j < end) {
            s_l = g_csr_src[j];
            float4 a4 = *(const float4*)(g_asrc + s_l * 4);
            x0 = __expf(lrelu(a4.x + adst4.x) - m0);
            x1 = __expf(lrelu(a4.y + adst4.y) - m1);
            x2 = __expf(lrelu(a4.z + adst4.z) - m2);
            x3 = __expf(lrelu(a4.w + adst4.w) - m3);
        }
        int cnt = min(32, end - jb);
        for (int k = 0; k < cnt; k++) {
            int s = __shfl_sync(FULLMASK, s_l, k);
            float e0 = __shfl_sync(FULLMASK, x0, k);
            float e1 = __shfl_sync(FULLMASK, x1, k);
            float e2 = __shfl_sync(FULLMASK, x2, k);
            float e3 = __shfl_sync(FULLMASK, x3, k);
            float ex = (myh == 0) ? e0 : (myh == 1) ? e1 : (myh == 2) ? e2 : e3;
            float4 hv = *(const float4*)(g_hp + s * 128 + lane * 4);
            a0 = fmaf(ex, hv.x, a0);
            a1 = fmaf(ex, hv.y, a1);
            a2 = fmaf(ex, hv.z, a2);
            a3 = fmaf(ex, hv.w, a3);
            den += ex;
        }
    }
    float inv = 1.f / fmaxf(den, 1e-16f);
    float4 bg = *(const float4*)(bgat + lane * 4);
    float v0 = a0 * inv + bg.x;
    float v1 = a1 * inv + bg.y;
    float v2 = a2 * inv + bg.z;
    float v3 = a3 * inv + bg.w;

    // LayerNorm over 128 (warp-wide)
    float s1 = v0 + v1 + v2 + v3;
#pragma unroll
    for (int o = 16; o > 0; o >>= 1) s1 += __shfl_xor_sync(FULLMASK, s1, o);
    float mu = s1 * (1.f / 128.f);
    float d0 = v0 - mu, d1 = v1 - mu, d2 = v2 - mu, d3 = v3 - mu;
    float s2 = d0 * d0 + d1 * d1 + d2 * d2 + d3 * d3;
#pragma unroll
    for (int o = 16; o > 0; o >>= 1) s2 += __shfl_xor_sync(FULLMASK, s2, o);
    float r = rsqrtf(s2 * (1.f / 128.f) + LN_EPS);
    float4 g4 = *(const float4*)(lng + lane * 4);
    float4 b4 = *(const float4*)(lnb + lane * 4);
    float o0 = fmaxf(d0 * r * g4.x + b4.x, 0.f);
    float o1 = fmaxf(d1 * r * g4.y + b4.y, 0.f);
    float o2 = fmaxf(d2 * r * g4.z + b4.z, 0.f);
    float o3 = fmaxf(d3 * r * g4.w + b4.w, 0.f);
    float4 res = *(const float4*)(g_h + n * 128 + lane * 4);
    float4 outv = make_float4(o0 + res.x, o1 + res.y, o2 + res.z, o3 + res.w);
    *(float4*)(g_h + n * 128 + lane * 4) = outv;
}

// ---------------- per-graph mean pooling (sorted batch, coalesced) ----------------
__global__ void k_pool(float* __restrict__ out) {
    int g = blockIdx.x;
    int d = threadIdx.x;  // 128 threads
    int s = g_gstart[g], e = g_gstart[g + 1];
    float acc = 0.f;
    for (int nn = s; nn < e; nn++) acc += g_h[nn * 128 + d];
    out[g * 128 + d] = acc / fmaxf((float)(e - s), 1.f);
}

// ---------------- launch ----------------
extern "C" void kernel_launch(void* const* d_in, const int* in_sizes, int n_in,
                              void* d_out, int out_size)
{
    const float* x      = (const float*)d_in[0];
    const float* W_in   = (const float*)d_in[1];
    const float* b_in   = (const float*)d_in[2];
    const float* W_gat  = (const float*)d_in[3];
    const float* att_src = (const float*)d_in[4];
    const float* att_dst = (const float*)d_in[5];
    const float* b_gat  = (const float*)d_in[6];
    const float* ln_g   = (const float*)d_in[7];
    const float* ln_b   = (const float*)d_in[8];
    const int*   ei     = (const int*)d_in[9];
    const int*   batch  = (const int*)d_in[10];
    float* out = (float*)d_out;

    float* h;  cudaGetSymbolAddress((void**)&h,  g_h);
    float* hp; cudaGetSymbolAddress((void**)&hp, g_hp);

    const int nscan = (N_NODES + SCAN_B - 1) / SCAN_B;  // 196

    k_zero<<<(N_NODES + 255) / 256, 256>>>();
    k_ehist<<<(ETOT + 255) / 256, 256>>>(ei);
    k_ghist<<<(N_NODES + 255) / 256, 256>>>(batch);
    k_scan1<<<nscan, SCAN_B>>>();
    k_scan2<<<1, 256>>>(nscan);
    k_scan3<<<nscan, SCAN_B>>>();
    k_copy_cursor<<<(N_NODES + 255) / 256, 256>>>();
    k_fill<<<(ETOT + 255) / 256, 256>>>(ei);
    k_gscan<<<1, NG>>>();

    gemm_tf32<IN_DIM, true><<<(N_NODES + 127) / 128, 256>>>(x, W_in, b_in, h);

    for (int l = 0; l < 3; l++) {
        gemm_tf32<HID, false><<<(N_NODES + 127) / 128, 256>>>(h, W_gat + l * HID * HID, nullptr, hp);
        k_scores<<<(N_NODES * 32 + 255) / 256, 256>>>(att_src + l * HID, att_dst + l * HID);
        k_agg<<<(N_NODES * 32 + 255) / 256, 256>>>(b_gat + l * HID, ln_g + l * HID, ln_b + l * HID);
    }

    k_pool<<<NG, HID>>>(out);
}

// round 2
// speedup vs baseline: 1.5486x; 1.5486x over previous
#include <cuda_runtime.h>
#include <cuda_fp16.h>
#include <cstdint>

#define N_NODES 100000
#define NE      1600000
#define ETOT    (NE + N_NODES)
#define NG      256
#define IN_DIM  480
#define HID     128
#define HEADS   4
#define NEG_SLOPE 0.2f
#define LN_EPS 1e-5f
#define ESHIFT 20.0f
#define FULLMASK 0xffffffffu

// ---------------- scratch (static device globals; no allocation) ----------------
__device__ __align__(16) float  g_h  [N_NODES * HID];   // fp32 running features
__device__ __align__(16) __half g_hph[N_NODES * HID];   // fp16 projected features (gather operand)
__device__ __align__(16) float g_asrc[N_NODES * HEADS];
__device__ __align__(16) float g_adst[N_NODES * HEADS];
__device__ int g_deg[N_NODES];
__device__ int g_rowptr[N_NODES + 1];
__device__ int g_cursor[N_NODES];
__device__ int g_csr_src[ETOT];
__device__ int g_bsums[256];
__device__ int g_gcnt[NG];
__device__ int g_gstart[NG + 1];

// ---------------- CSR build ----------------
__global__ void k_zero() {
    int i = blockIdx.x * blockDim.x + threadIdx.x;
    if (i < N_NODES) g_deg[i] = 0;
    if (i < NG) g_gcnt[i] = 0;
}

__global__ void k_ehist(const int* __restrict__ ei) {
    int i = blockIdx.x * blockDim.x + threadIdx.x;
    if (i >= ETOT) return;
    int d = (i < NE) ? ei[NE + i] : (i - NE);
    atomicAdd(&g_deg[d], 1);
}

__global__ void k_ghist(const int* __restrict__ batch) {
    int i = blockIdx.x * blockDim.x + threadIdx.x;
    if (i < N_NODES) atomicAdd(&g_gcnt[batch[i]], 1);
}

#define SCAN_B 512
__global__ void k_scan1() {
    __shared__ int sm[SCAN_B];
    int t = threadIdx.x;
    int i = blockIdx.x * SCAN_B + t;
    int v = (i < N_NODES) ? g_deg[i] : 0;
    sm[t] = v; __syncthreads();
    for (int o = 1; o < SCAN_B; o <<= 1) {
        int u = (t >= o) ? sm[t - o] : 0;
        __syncthreads();
        sm[t] += u;
        __syncthreads();
    }
    if (i < N_NODES) g_rowptr[i + 1] = sm[t];
    if (t == SCAN_B - 1) g_bsums[blockIdx.x] = sm[t];
}

__global__ void k_scan2(int nb) {
    __shared__ int sm[256];
    int t = threadIdx.x;
    int v = (t < nb) ? g_bsums[t] : 0;
    sm[t] = v; __syncthreads();
    for (int o = 1; o < 256; o <<= 1) {
        int u = (t >= o) ? sm[t - o] : 0;
        __syncthreads();
        sm[t] += u;
        __syncthreads();
    }
    if (t < nb) g_bsums[t] = sm[t] - v;  // exclusive
}

__global__ void k_scan3() {
    int i = blockIdx.x * SCAN_B + threadIdx.x;
    if (i < N_NODES) g_rowptr[i + 1] += g_bsums[blockIdx.x];
    if (i == 0) g_rowptr[0] = 0;
}

__global__ void k_copy_cursor() {
    int i = blockIdx.x * blockDim.x + threadIdx.x;
    if (i < N_NODES) g_cursor[i] = g_rowptr[i];
}

__global__ void k_fill(const int* __restrict__ ei) {
    int i = blockIdx.x * blockDim.x + threadIdx.x;
    if (i >= ETOT) return;
    int s, d;
    if (i < NE) { s = ei[i]; d = ei[NE + i]; }
    else        { s = d = i - NE; }
    int pos = atomicAdd(&g_cursor[d], 1);
    g_csr_src[pos] = s;
}

__global__ void k_gscan() {
    __shared__ int sm[NG];
    int t = threadIdx.x;
    int v = g_gcnt[t];
    sm[t] = v; __syncthreads();
    for (int o = 1; o < NG; o <<= 1) {
        int u = (t >= o) ? sm[t - o] : 0;
        __syncthreads();
        sm[t] += u;
        __syncthreads();
    }
    g_gstart[t] = sm[t] - v;
    if (t == NG - 1) g_gstart[NG] = sm[t];
}

// ---------------- tf32 tensor-core GEMM, cp.async 2-stage pipeline ----------------
__device__ __forceinline__ float f2tf32(float x) {
    asm("cvt.rna.tf32.f32 %0, %1;" : "=f"(x) : "f"(x));
    return x;
}

__device__ __forceinline__ void mma_tf32(float* c, const unsigned* a, const unsigned* b) {
    asm volatile(
        "mma.sync.aligned.m16n8k8.row.col.f32.tf32.tf32.f32 "
        "{%0,%1,%2,%3},{%4,%5,%6,%7},{%8,%9},{%0,%1,%2,%3};\n"
        : "+f"(c[0]), "+f"(c[1]), "+f"(c[2]), "+f"(c[3])
        : "r"(a[0]), "r"(a[1]), "r"(a[2]), "r"(a[3]), "r"(b[0]), "r"(b[1]));
}

// C[M,128] = A[M,KD] @ B[KD,128]
// RELU_BIAS=true : out = relu(C+bias) -> Cf (fp32)
// RELU_BIAS=false: out = C -> Ch (fp16)
template <int KD, bool RELU_BIAS>
__global__ __launch_bounds__(256) void gemm_tf32(
    const float* __restrict__ A, const float* __restrict__ B,
    const float* __restrict__ bias, float* __restrict__ Cf, __half* __restrict__ Ch)
{
    constexpr int NIT = KD / 16;
    // As: [m][k] 128x16 floats, 16B segments XOR-swizzled by ((m>>1)&3)
    // Bs: [k][n] 16x136 floats (pad 8 -> conflict-free column fragment loads)
    __shared__ float As[2][128 * 16];
    __shared__ float Bs[2][16 * 136];
    int tid = threadIdx.x;
    int warp = tid >> 5, lane = tid & 31;
    int wm = warp >> 1, wn = warp & 1;
    int gid = lane >> 2, tg = lane & 3;
    int rowBase = blockIdx.x * 128;

    float acc[2][8][4];
#pragma unroll
    for (int mf = 0; mf < 2; mf++)
#pragma unroll
        for (int nf = 0; nf < 8; nf++)
#pragma unroll
            for (int q = 0; q < 4; q++) acc[mf][nf][q] = 0.f;

    auto loadStage = [&](int st, int k0) {
#pragma unroll
        for (int i = 0; i < 2; i++) {
            int id = tid + i * 256;
            int row = id >> 2, seg = id & 3;
            int gr = rowBase + row;
            const float* src = A + (size_t)(gr < N_NODES ? gr : 0) * KD + k0 + seg * 4;
            uint32_t dst = (uint32_t)__cvta_generic_to_shared(
                &As[st][row * 16 + ((seg ^ ((row >> 1) & 3)) << 2)]);
            int sz = (gr < N_NODES) ? 16 : 0;
            asm volatile("cp.async.cg.shared.global [%0], [%1], 16, %2;\n"
                         :: "r"(dst), "l"(src), "r"(sz));
        }
#pragma unroll
        for (int i = 0; i < 2; i++) {
            int id = tid + i * 256;
            int row = id >> 5, c = (id & 31) * 4;
            const float* src = B + (size_t)(k0 + row) * 128 + c;
            uint32_t dst = (uint32_t)__cvta_generic_to_shared(&Bs[st][row * 136 + c]);
            asm volatile("cp.async.cg.shared.global [%0], [%1], 16;\n"
                         :: "r"(dst), "l"(src));
        }
        asm volatile("cp.async.commit_group;\n");
    };

    loadStage(0, 0);
    for (int it = 0; it < NIT; it++) {
        if (it + 1 < NIT) {
            loadStage((it + 1) & 1, (it + 1) * 16);
            asm volatile("cp.async.wait_group 1;\n");
        } else {
            asm volatile("cp.async.wait_group 0;\n");
        }
        __syncthreads();
        const float* as = As[it & 1];
        const float* bs = Bs[it & 1];
#pragma unroll
        for (int ks = 0; ks < 2; ks++) {
            int kb = ks * 8;
            unsigned afr[2][4];
            unsigned bfr[8][2];
#pragma unroll
            for (int mf = 0; mf < 2; mf++) {
                int mB = wm * 32 + mf * 16 + gid;
#pragma unroll
                for (int q = 0; q < 4; q++) {
                    int m = mB + (q & 1) * 8;
                    int seg = ks * 2 + (q >> 1);
                    float v = as[m * 16 + ((seg ^ ((m >> 1) & 3)) << 2) + tg];
                    afr[mf][q] = __float_as_uint(f2tf32(v));
                }
            }
#pragma unroll
            for (int nf = 0; nf < 8; nf++) {
                int n = wn * 64 + nf * 8 + gid;
                bfr[nf][0] = __float_as_uint(f2tf32(bs[(kb + tg) * 136 + n]));
                bfr[nf][1] = __float_as_uint(f2tf32(bs[(kb + tg + 4) * 136 + n]));
            }
#pragma unroll
            for (int mf = 0; mf < 2; mf++)
#pragma unroll
                for (int nf = 0; nf < 8; nf++)
                    mma_tf32(acc[mf][nf], afr[mf], bfr[nf]);
        }
        __syncthreads();
    }

    // epilogue
#pragma unroll
    for (int mf = 0; mf < 2; mf++) {
        int r0 = rowBase + wm * 32 + mf * 16 + gid;
#pragma unroll
        for (int nf = 0; nf < 8; nf++) {
            int c = wn * 64 + nf * 8 + tg * 2;
            if (RELU_BIAS) {
                float b0 = __ldg(bias + c), b1 = __ldg(bias + c + 1);
                float2 v0 = make_float2(fmaxf(acc[mf][nf][0] + b0, 0.f),
                                        fmaxf(acc[mf][nf][1] + b1, 0.f));
                float2 v1 = make_float2(fmaxf(acc[mf][nf][2] + b0, 0.f),
                                        fmaxf(acc[mf][nf][3] + b1, 0.f));
                if (r0 < N_NODES)     *(float2*)(Cf + (size_t)r0 * 128 + c) = v0;
                if (r0 + 8 < N_NODES) *(float2*)(Cf + (size_t)(r0 + 8) * 128 + c) = v1;
            } else {
                if (r0 < N_NODES)
                    *(__half2*)(Ch + (size_t)r0 * 128 + c) =
                        __floats2half2_rn(acc[mf][nf][0], acc[mf][nf][1]);
                if (r0 + 8 < N_NODES)
                    *(__half2*)(Ch + (size_t)(r0 + 8) * 128 + c) =
                        __floats2half2_rn(acc[mf][nf][2], acc[mf][nf][3]);
            }
        }
    }
}

// ---------------- attention scores: asrc/adst [N,4] from fp16 hp ----------------
__global__ void k_scores(const float* __restrict__ att_s, const float* __restrict__ att_d) {
    int gi = blockIdx.x * blockDim.x + threadIdx.x;
    int n = gi >> 5;
    if (n >= N_NODES) return;
    int lane = threadIdx.x & 31;
    uint2 hv = *(const uint2*)(g_hph + (size_t)n * 128 + lane * 4);
    float2 lo = __half22float2(*(__half2*)&hv.x);
    float2 hi = __half22float2(*(__half2*)&hv.y);
    float4 as = *(const float4*)(att_s + lane * 4);
    float4 ad = *(const float4*)(att_d + lane * 4);
    float ss = lo.x * as.x + lo.y * as.y + hi.x * as.z + hi.y * as.w;
    float sd = lo.x * ad.x + lo.y * ad.y + hi.x * ad.z + hi.y * ad.w;
#pragma unroll
    for (int o = 4; o > 0; o >>= 1) {
        ss += __shfl_down_sync(FULLMASK, ss, o);
        sd += __shfl_down_sync(FULLMASK, sd, o);
    }
    if ((lane & 7) == 0) {
        g_asrc[n * 4 + (lane >> 3)] = ss;
        g_adst[n * 4 + (lane >> 3)] = sd;
    }
}

// ---------------- fused GAT aggregation + bias + LN + relu + residual ----------------
__device__ __forceinline__ float lrelu(float x) { return x > 0.f ? x : NEG_SLOPE * x; }

__global__ __launch_bounds__(256) void k_agg(
    const float* __restrict__ bgat, const float* __restrict__ lng, const float* __restrict__ lnb)
{
    __shared__ float s_ex[8][128];
    __shared__ int   s_src[8][32];
    int warp = threadIdx.x >> 5, lane = threadIdx.x & 31;
    int n = blockIdx.x * 8 + warp;
    if (n >= N_NODES) return;
    int myh = lane >> 3;
    int beg = g_rowptr[n], end = g_rowptr[n + 1];
    float4 adst4 = *(const float4*)(g_adst + n * 4);

    float a0 = 0.f, a1 = 0.f, a2 = 0.f, a3 = 0.f, den = 0.f;
    for (int jb = beg; jb < end; jb += 32) {
        int j = jb + lane;
        bool v = j < end;
        int s = v ? g_csr_src[j] : 0;
        float4 a4 = *(const float4*)(g_asrc + s * 4);
        float e0 = v ? __expf(lrelu(a4.x + adst4.x) - ESHIFT) : 0.f;
        float e1 = v ? __expf(lrelu(a4.y + adst4.y) - ESHIFT) : 0.f;
        float e2 = v ? __expf(lrelu(a4.z + adst4.z) - ESHIFT) : 0.f;
        float e3 = v ? __expf(lrelu(a4.w + adst4.w) - ESHIFT) : 0.f;
        s_src[warp][lane] = s;
        *(float4*)&s_ex[warp][lane * 4] = make_float4(e0, e1, e2, e3);
        __syncwarp();
        int cnt = min(32, end - jb);
#pragma unroll 4
        for (int k = 0; k < cnt; k++) {
            int ss = s_src[warp][k];
            float e = s_ex[warp][k * 4 + myh];
            uint2 hv = *(const uint2*)(g_hph + (size_t)ss * 128 + lane * 4);
            float2 lo = __half22float2(*(__half2*)&hv.x);
            float2 hi = __half22float2(*(__half2*)&hv.y);
            a0 = fmaf(e, lo.x, a0);
            a1 = fmaf(e, lo.y, a1);
            a2 = fmaf(e, hi.x, a2);
            a3 = fmaf(e, hi.y, a3);
            den += e;
        }
        __syncwarp();
    }
    float inv = 1.f / fmaxf(den, 1e-38f);
    float4 bg = *(const float4*)(bgat + lane * 4);
    float v0 = a0 * inv + bg.x;
    float v1 = a1 * inv + bg.y;
    float v2 = a2 * inv + bg.z;
    float v3 = a3 * inv + bg.w;

    // LayerNorm over 128 (warp-wide)
    float s1 = v0 + v1 + v2 + v3;
#pragma unroll
    for (int o = 16; o > 0; o >>= 1) s1 += __shfl_xor_sync(FULLMASK, s1, o);
    float mu = s1 * (1.f / 128.f);
    float d0 = v0 - mu, d1 = v1 - mu, d2 = v2 - mu, d3 = v3 - mu;
    float s2 = d0 * d0 + d1 * d1 + d2 * d2 + d3 * d3;
#pragma unroll
    for (int o = 16; o > 0; o >>= 1) s2 += __shfl_xor_sync(FULLMASK, s2, o);
    float r = rsqrtf(s2 * (1.f / 128.f) + LN_EPS);
    float4 g4 = *(const float4*)(lng + lane * 4);
    float4 b4 = *(const float4*)(lnb + lane * 4);
    float o0 = fmaxf(d0 * r * g4.x + b4.x, 0.f);
    float o1 = fmaxf(d1 * r * g4.y + b4.y, 0.f);
    float o2 = fmaxf(d2 * r * g4.z + b4.z, 0.f);
    float o3 = fmaxf(d3 * r * g4.w + b4.w, 0.f);
    float4 res = *(const float4*)(g_h + (size_t)n * 128 + lane * 4);
    float4 outv = make_float4(o0 + res.x, o1 + res.y, o2 + res.z, o3 + res.w);
    *(float4*)(g_h + (size_t)n * 128 + lane * 4) = outv;
}

// ---------------- per-graph mean pooling (sorted batch, coalesced) ----------------
__global__ void k_pool(float* __restrict__ out) {
    int g = blockIdx.x;
    int d = threadIdx.x;  // 128 threads
    int s = g_gstart[g], e = g_gstart[g + 1];
    float acc = 0.f;
    for (int nn = s; nn < e; nn++) acc += g_h[(size_t)nn * 128 + d];
    out[g * 128 + d] = acc / fmaxf((float)(e - s), 1.f);
}

// ---------------- launch ----------------
extern "C" void kernel_launch(void* const* d_in, const int* in_sizes, int n_in,
                              void* d_out, int out_size)
{
    const float* x       = (const float*)d_in[0];
    const float* W_in    = (const float*)d_in[1];
    const float* b_in    = (const float*)d_in[2];
    const float* W_gat   = (const float*)d_in[3];
    const float* att_src = (const float*)d_in[4];
    const float* att_dst = (const float*)d_in[5];
    const float* b_gat   = (const float*)d_in[6];
    const float* ln_g    = (const float*)d_in[7];
    const float* ln_b    = (const float*)d_in[8];
    const int*   ei      = (const int*)d_in[9];
    const int*   batch   = (const int*)d_in[10];
    float* out = (float*)d_out;

    float*  h;   cudaGetSymbolAddress((void**)&h,   g_h);
    __half* hph; cudaGetSymbolAddress((void**)&hph, g_hph);

    const int nscan = (N_NODES + SCAN_B - 1) / SCAN_B;

    k_zero<<<(N_NODES + 255) / 256, 256>>>();
    k_ehist<<<(ETOT + 255) / 256, 256>>>(ei);
    k_ghist<<<(N_NODES + 255) / 256, 256>>>(batch);
    k_scan1<<<nscan, SCAN_B>>>();
    k_scan2<<<1, 256>>>(nscan);
    k_scan3<<<nscan, SCAN_B>>>();
    k_copy_cursor<<<(N_NODES + 255) / 256, 256>>>();
    k_fill<<<(ETOT + 255) / 256, 256>>>(ei);
    k_gscan<<<1, NG>>>();

    gemm_tf32<IN_DIM, true><<<(N_NODES + 127) / 128, 256>>>(x, W_in, b_in, h, nullptr);

    for (int l = 0; l < 3; l++) {
        gemm_tf32<HID, false><<<(N_NODES + 127) / 128, 256>>>(
            h, W_gat + l * HID * HID, nullptr, nullptr, hph);
        k_scores<<<(N_NODES * 32 + 255) / 256, 256>>>(att_src + l * HID, att_dst + l * HID);
        k_agg<<<(N_NODES + 7) / 8, 256>>>(b_gat + l * HID, ln_g + l * HID, ln_b + l * HID);
    }

    k_pool<<<NG, HID>>>(out);
}